// round 2
// baseline (speedup 1.0000x reference)
#include <cuda_runtime.h>
#include <cuda_bf16.h>
#include <cstdint>

#define NN 100000
#define EE 3200000
#define NC 64
#define TOPK 16
#define NHID 128
#define DEG 6
#define SCAN_BS 1024
#define SCAN_NB ((NN + SCAN_BS - 1) / SCAN_BS)   // 98

// ---------------- device scratch (static allocation only) ----------------
__device__ int   g_count[NN];
__device__ int   g_rowstart[NN + 1];
__device__ int   g_cursor[NN];
__device__ int   g_partials[128];
__device__ int2  g_csr[EE];                       // (col, val bits)
__device__ float g_cur[2][(size_t)NN * NC];
__device__ float g_out[(size_t)NN * NC];
__device__ float g_weight[NN * DEG];

// ---------------- CSR build ----------------
__global__ void k_zero_count() {
    int i = blockIdx.x * blockDim.x + threadIdx.x;
    if (i < NN) g_count[i] = 0;
}

__global__ void k_hist(const int* __restrict__ er) {
    int i = blockIdx.x * blockDim.x + threadIdx.x;
    if (i < EE) atomicAdd(&g_count[er[i]], 1);
}

__global__ void k_scan1() {
    __shared__ int sh[SCAN_BS];
    int i = blockIdx.x * SCAN_BS + threadIdx.x;
    int v = (i < NN) ? g_count[i] : 0;
    sh[threadIdx.x] = v;
    __syncthreads();
    for (int o = 1; o < SCAN_BS; o <<= 1) {
        int t = (threadIdx.x >= o) ? sh[threadIdx.x - o] : 0;
        __syncthreads();
        sh[threadIdx.x] += t;
        __syncthreads();
    }
    if (i < NN) g_rowstart[i] = sh[threadIdx.x] - v;      // exclusive within block
    if (threadIdx.x == SCAN_BS - 1) g_partials[blockIdx.x] = sh[threadIdx.x];
}

__global__ void k_scan2(int nb) {
    __shared__ int sh[128];
    int v = (threadIdx.x < nb) ? g_partials[threadIdx.x] : 0;
    sh[threadIdx.x] = v;
    __syncthreads();
    for (int o = 1; o < 128; o <<= 1) {
        int t = (threadIdx.x >= o) ? sh[threadIdx.x - o] : 0;
        __syncthreads();
        sh[threadIdx.x] += t;
        __syncthreads();
    }
    if (threadIdx.x < nb) g_partials[threadIdx.x] = sh[threadIdx.x] - v;  // exclusive
}

__global__ void k_scan3() {
    int i = blockIdx.x * SCAN_BS + threadIdx.x;
    if (i < NN) {
        int r = g_rowstart[i] + g_partials[blockIdx.x];
        g_rowstart[i] = r;
        g_cursor[i]   = r;
    }
    if (i == 0) g_rowstart[NN] = EE;
}

__global__ void k_scatter(const int* __restrict__ er,
                          const int* __restrict__ ec,
                          const float* __restrict__ ev) {
    int i = blockIdx.x * blockDim.x + threadIdx.x;
    if (i >= EE) return;
    int r = er[i];
    int c = ec[i];
    float v = ev[i];
    int pos = atomicAdd(&g_cursor[r], 1);
    g_csr[pos] = make_int2(c, __float_as_int(v));
}

// ---------------- gating: softmax -> top16 -> MLP -> hop weights ----------------
__global__ void k_gating(const float* __restrict__ x,
                         const float* __restrict__ W1, const float* __restrict__ b1,
                         const float* __restrict__ W2, const float* __restrict__ b2) {
    int warp = (blockIdx.x * blockDim.x + threadIdx.x) >> 5;
    if (warp >= NN) return;
    int lane = threadIdx.x & 31;

    float2 xv = *(const float2*)(x + (size_t)warp * NC + 2 * lane);

    // softmax over 64
    float m = fmaxf(xv.x, xv.y);
    #pragma unroll
    for (int o = 16; o; o >>= 1) m = fmaxf(m, __shfl_xor_sync(~0u, m, o));
    float e0 = __expf(xv.x - m), e1 = __expf(xv.y - m);
    float s = e0 + e1;
    #pragma unroll
    for (int o = 16; o; o >>= 1) s += __shfl_xor_sync(~0u, s, o);
    float inv = 1.0f / s;
    float a0 = e0 * inv, a1 = e1 * inv;

    // top-16, descending, index tie-break (matches jax.lax.top_k)
    float tk[TOPK];
    #pragma unroll
    for (int i = 0; i < TOPK; i++) {
        float lv; int li;
        if (a0 >= a1) { lv = a0; li = 2 * lane; } else { lv = a1; li = 2 * lane + 1; }
        #pragma unroll
        for (int o = 16; o; o >>= 1) {
            float ov = __shfl_xor_sync(~0u, lv, o);
            int   oi = __shfl_xor_sync(~0u, li, o);
            if (ov > lv || (ov == lv && oi < li)) { lv = ov; li = oi; }
        }
        tk[i] = lv;
        if ((li >> 1) == lane) { if (li & 1) a1 = -1.0f; else a0 = -1.0f; }
    }

    // layer 1: h = leaky_relu(tk @ W1^T + b1), each lane owns 4 hidden units
    float h[4];
    #pragma unroll
    for (int j = 0; j < 4; j++) {
        int r = lane + 32 * j;
        float acc = b1[r];
        #pragma unroll
        for (int k = 0; k < TOPK; k++) acc += tk[k] * __ldg(&W1[r * TOPK + k]);
        h[j] = (acc >= 0.0f) ? acc : 0.1f * acc;
    }

    // layer 2: 6 logits, butterfly-reduced so all lanes hold them
    float lg[DEG];
    #pragma unroll
    for (int d = 0; d < DEG; d++) {
        float acc = 0.0f;
        #pragma unroll
        for (int j = 0; j < 4; j++) acc += h[j] * __ldg(&W2[d * NHID + lane + 32 * j]);
        #pragma unroll
        for (int o = 16; o; o >>= 1) acc += __shfl_xor_sync(~0u, acc, o);
        lg[d] = acc + b2[d];
    }

    // softmax over 6 hops
    float mm = lg[0];
    #pragma unroll
    for (int d = 1; d < DEG; d++) mm = fmaxf(mm, lg[d]);
    float ss = 0.0f;
    #pragma unroll
    for (int d = 0; d < DEG; d++) { lg[d] = __expf(lg[d] - mm); ss += lg[d]; }
    float invs = 1.0f / ss;
    if (lane < DEG) g_weight[warp * DEG + lane] = lg[lane] * invs;

    // out init: out = w0 * x
    float w0 = lg[0] * invs;
    *(float2*)(g_out + (size_t)warp * NC + 2 * lane) = make_float2(w0 * xv.x, w0 * xv.y);
}

// ---------------- SpMM gather + fused axpy (out += w_hop * next) ----------------
__global__ void __launch_bounds__(256) k_spmm(const float* __restrict__ xin,
                                              int srcsel, int dstsel, int hop) {
    int gtid = blockIdx.x * blockDim.x + threadIdx.x;
    int row = gtid >> 4;                 // 16 lanes per row, 2 rows per warp
    if (row >= NN) return;
    int sub = threadIdx.x & 15;

    const float* __restrict__ cur = (srcsel < 0) ? xin : g_cur[srcsel];
    float* __restrict__ next = g_cur[dstsel];

    int s = g_rowstart[row], e = g_rowstart[row + 1];
    float4 acc = make_float4(0.f, 0.f, 0.f, 0.f);

    int i = s;
    for (; i + 2 <= e; i += 2) {
        int2 e0 = __ldg(&g_csr[i]);
        int2 e1 = __ldg(&g_csr[i + 1]);
        float4 c0 = *(const float4*)(cur + (size_t)e0.x * NC + sub * 4);
        float4 c1 = *(const float4*)(cur + (size_t)e1.x * NC + sub * 4);
        float v0 = __int_as_float(e0.y), v1 = __int_as_float(e1.y);
        acc.x += v0 * c0.x + v1 * c1.x;
        acc.y += v0 * c0.y + v1 * c1.y;
        acc.z += v0 * c0.z + v1 * c1.z;
        acc.w += v0 * c0.w + v1 * c1.w;
    }
    if (i < e) {
        int2 e0 = __ldg(&g_csr[i]);
        float4 c0 = *(const float4*)(cur + (size_t)e0.x * NC + sub * 4);
        float v0 = __int_as_float(e0.y);
        acc.x += v0 * c0.x; acc.y += v0 * c0.y;
        acc.z += v0 * c0.z; acc.w += v0 * c0.w;
    }

    size_t off = (size_t)row * NC + sub * 4;
    *(float4*)(next + off) = acc;

    float w = g_weight[row * DEG + hop];
    float4 o = *(const float4*)(g_out + off);
    o.x += w * acc.x; o.y += w * acc.y; o.z += w * acc.z; o.w += w * acc.w;
    *(float4*)(g_out + off) = o;
}

// ---------------- final log_softmax ----------------
__global__ void k_final(float* __restrict__ dout) {
    int warp = (blockIdx.x * blockDim.x + threadIdx.x) >> 5;
    if (warp >= NN) return;
    int lane = threadIdx.x & 31;
    float2 t = *(const float2*)(g_out + (size_t)warp * NC + 2 * lane);
    float m = fmaxf(t.x, t.y);
    #pragma unroll
    for (int o = 16; o; o >>= 1) m = fmaxf(m, __shfl_xor_sync(~0u, m, o));
    float s = __expf(t.x - m) + __expf(t.y - m);
    #pragma unroll
    for (int o = 16; o; o >>= 1) s += __shfl_xor_sync(~0u, s, o);
    float l = m + __logf(s);
    *(float2*)(dout + (size_t)warp * NC + 2 * lane) = make_float2(t.x - l, t.y - l);
}

// ---------------- launch ----------------
extern "C" void kernel_launch(void* const* d_in, const int* in_sizes, int n_in,
                              void* d_out, int out_size) {
    const float* x  = (const float*)d_in[0];
    const int*   er = (const int*)d_in[1];
    const int*   ec = (const int*)d_in[2];
    const float* ev = (const float*)d_in[3];
    const float* W1 = (const float*)d_in[4];
    const float* b1 = (const float*)d_in[5];
    const float* W2 = (const float*)d_in[6];
    const float* b2 = (const float*)d_in[7];
    float* out = (float*)d_out;

    k_zero_count<<<(NN + 255) / 256, 256>>>();
    k_hist<<<(EE + 255) / 256, 256>>>(er);
    k_scan1<<<SCAN_NB, SCAN_BS>>>();
    k_scan2<<<1, 128>>>(SCAN_NB);
    k_scan3<<<SCAN_NB, SCAN_BS>>>();
    k_scatter<<<(EE + 255) / 256, 256>>>(er, ec, ev);

    k_gating<<<(NN * 32 + 255) / 256, 256>>>(x, W1, b1, W2, b2);

    k_spmm<<<(NN * 16 + 255) / 256, 256>>>(x, -1, 0, 1);
    k_spmm<<<(NN * 16 + 255) / 256, 256>>>(nullptr, 0, 1, 2);
    k_spmm<<<(NN * 16 + 255) / 256, 256>>>(nullptr, 1, 0, 3);
    k_spmm<<<(NN * 16 + 255) / 256, 256>>>(nullptr, 0, 1, 4);
    k_spmm<<<(NN * 16 + 255) / 256, 256>>>(nullptr, 1, 0, 5);

    k_final<<<(NN * 32 + 255) / 256, 256>>>(out);
}

// round 3
// speedup vs baseline: 1.1582x; 1.1582x over previous
#include <cuda_runtime.h>
#include <cuda_fp16.h>
#include <cstdint>

#define NN 100000
#define EE 3200000
#define NC 64
#define TOPK 16
#define NHID 128
#define DEG 6
#define SCAN_BS 1024
#define SCAN_NB ((NN + SCAN_BS - 1) / SCAN_BS)   // 98

// ---------------- device scratch (static allocation only) ----------------
__device__ int   g_count[NN];            // zero at module load; self-restored each call
__device__ int   g_rowstart[NN + 1];
__device__ int   g_cursor[NN];
__device__ int   g_partials[128];
__device__ int2  g_csr[EE];              // (col, val bits)
__device__ __align__(16) __half g_xh[(size_t)NN * NC];       // fp16 copy of x
__device__ __align__(16) __half g_curh[2][(size_t)NN * NC];  // fp16 hop features
__device__ float g_out[(size_t)NN * NC];
__device__ float g_weight[NN * DEG];

// ---------------- CSR build ----------------
__global__ void k_hist(const int* __restrict__ er) {
    int i = blockIdx.x * blockDim.x + threadIdx.x;
    if (i < EE) atomicAdd(&g_count[er[i]], 1);
}

__global__ void k_scan1() {
    __shared__ int sh[SCAN_BS];
    int i = blockIdx.x * SCAN_BS + threadIdx.x;
    int v = (i < NN) ? g_count[i] : 0;
    if (i < NN) g_count[i] = 0;                 // restore for next call
    sh[threadIdx.x] = v;
    __syncthreads();
    for (int o = 1; o < SCAN_BS; o <<= 1) {
        int t = (threadIdx.x >= o) ? sh[threadIdx.x - o] : 0;
        __syncthreads();
        sh[threadIdx.x] += t;
        __syncthreads();
    }
    if (i < NN) g_rowstart[i] = sh[threadIdx.x] - v;      // exclusive within block
    if (threadIdx.x == SCAN_BS - 1) g_partials[blockIdx.x] = sh[threadIdx.x];
}

__global__ void k_scan2(int nb) {
    __shared__ int sh[128];
    int v = (threadIdx.x < nb) ? g_partials[threadIdx.x] : 0;
    sh[threadIdx.x] = v;
    __syncthreads();
    for (int o = 1; o < 128; o <<= 1) {
        int t = (threadIdx.x >= o) ? sh[threadIdx.x - o] : 0;
        __syncthreads();
        sh[threadIdx.x] += t;
        __syncthreads();
    }
    if (threadIdx.x < nb) g_partials[threadIdx.x] = sh[threadIdx.x] - v;  // exclusive
}

__global__ void k_scan3() {
    int i = blockIdx.x * SCAN_BS + threadIdx.x;
    if (i < NN) {
        int r = g_rowstart[i] + g_partials[blockIdx.x];
        g_rowstart[i] = r;
        g_cursor[i]   = r;
    }
    if (i == 0) g_rowstart[NN] = EE;
}

__global__ void k_scatter(const int* __restrict__ er,
                          const int* __restrict__ ec,
                          const float* __restrict__ ev) {
    int i = blockIdx.x * blockDim.x + threadIdx.x;
    if (i >= EE) return;
    int r = er[i];
    int c = ec[i];
    float v = ev[i];
    int pos = atomicAdd(&g_cursor[r], 1);
    g_csr[pos] = make_int2(c, __float_as_int(v));
}

// ------- gating: softmax -> top16 -> MLP -> hop weights; also emits x as fp16 -------
__global__ void k_gating(const float* __restrict__ x,
                         const float* __restrict__ W1, const float* __restrict__ b1,
                         const float* __restrict__ W2, const float* __restrict__ b2) {
    int warp = (blockIdx.x * blockDim.x + threadIdx.x) >> 5;
    if (warp >= NN) return;
    int lane = threadIdx.x & 31;

    float2 xv = *(const float2*)(x + (size_t)warp * NC + 2 * lane);

    // fp16 copy of x for hop-1 gather
    *(__half2*)(g_xh + (size_t)warp * NC + 2 * lane) = __floats2half2_rn(xv.x, xv.y);

    // softmax over 64
    float m = fmaxf(xv.x, xv.y);
    #pragma unroll
    for (int o = 16; o; o >>= 1) m = fmaxf(m, __shfl_xor_sync(~0u, m, o));
    float e0 = __expf(xv.x - m), e1 = __expf(xv.y - m);
    float s = e0 + e1;
    #pragma unroll
    for (int o = 16; o; o >>= 1) s += __shfl_xor_sync(~0u, s, o);
    float inv = 1.0f / s;
    float a0 = e0 * inv, a1 = e1 * inv;

    // top-16, descending, index tie-break (matches jax.lax.top_k)
    float tk[TOPK];
    #pragma unroll
    for (int i = 0; i < TOPK; i++) {
        float lv; int li;
        if (a0 >= a1) { lv = a0; li = 2 * lane; } else { lv = a1; li = 2 * lane + 1; }
        #pragma unroll
        for (int o = 16; o; o >>= 1) {
            float ov = __shfl_xor_sync(~0u, lv, o);
            int   oi = __shfl_xor_sync(~0u, li, o);
            if (ov > lv || (ov == lv && oi < li)) { lv = ov; li = oi; }
        }
        tk[i] = lv;
        if ((li >> 1) == lane) { if (li & 1) a1 = -1.0f; else a0 = -1.0f; }
    }

    // layer 1: h = leaky_relu(tk @ W1^T + b1), each lane owns 4 hidden units
    float h[4];
    #pragma unroll
    for (int j = 0; j < 4; j++) {
        int r = lane + 32 * j;
        float acc = b1[r];
        #pragma unroll
        for (int k = 0; k < TOPK; k++) acc += tk[k] * __ldg(&W1[r * TOPK + k]);
        h[j] = (acc >= 0.0f) ? acc : 0.1f * acc;
    }

    // layer 2: 6 logits, butterfly-reduced so all lanes hold them
    float lg[DEG];
    #pragma unroll
    for (int d = 0; d < DEG; d++) {
        float acc = 0.0f;
        #pragma unroll
        for (int j = 0; j < 4; j++) acc += h[j] * __ldg(&W2[d * NHID + lane + 32 * j]);
        #pragma unroll
        for (int o = 16; o; o >>= 1) acc += __shfl_xor_sync(~0u, acc, o);
        lg[d] = acc + b2[d];
    }

    // softmax over 6 hops
    float mm = lg[0];
    #pragma unroll
    for (int d = 1; d < DEG; d++) mm = fmaxf(mm, lg[d]);
    float ss = 0.0f;
    #pragma unroll
    for (int d = 0; d < DEG; d++) { lg[d] = __expf(lg[d] - mm); ss += lg[d]; }
    float invs = 1.0f / ss;
    if (lane < DEG) g_weight[warp * DEG + lane] = lg[lane] * invs;

    // out init: out = w0 * x   (fp32 exact)
    float w0 = lg[0] * invs;
    *(float2*)(g_out + (size_t)warp * NC + 2 * lane) = make_float2(w0 * xv.x, w0 * xv.y);
}

// -------- SpMM gather (fp16 features, fp32 accum) + fused axpy into fp32 out --------
__device__ __forceinline__ void mac8(float* acc, uint4 raw, float v) {
    __half2 h0 = *(__half2*)&raw.x, h1 = *(__half2*)&raw.y;
    __half2 h2 = *(__half2*)&raw.z, h3 = *(__half2*)&raw.w;
    float2 f0 = __half22float2(h0), f1 = __half22float2(h1);
    float2 f2 = __half22float2(h2), f3 = __half22float2(h3);
    acc[0] += v * f0.x; acc[1] += v * f0.y;
    acc[2] += v * f1.x; acc[3] += v * f1.y;
    acc[4] += v * f2.x; acc[5] += v * f2.y;
    acc[6] += v * f3.x; acc[7] += v * f3.y;
}

__global__ void __launch_bounds__(256) k_spmm(int srcsel, int dstsel, int hop) {
    int gtid = blockIdx.x * blockDim.x + threadIdx.x;
    int row = gtid >> 3;                 // 8 lanes per row
    if (row >= NN) return;
    int sub = threadIdx.x & 7;

    const __half* __restrict__ cur = (srcsel < 0) ? g_xh : g_curh[srcsel];
    __half* __restrict__ next = g_curh[dstsel];

    int s = g_rowstart[row], e = g_rowstart[row + 1];
    float acc[8];
    #pragma unroll
    for (int j = 0; j < 8; j++) acc[j] = 0.0f;

    int i = s;
    for (; i + 4 <= e; i += 4) {
        int2 e0 = __ldg(&g_csr[i]);
        int2 e1 = __ldg(&g_csr[i + 1]);
        int2 e2 = __ldg(&g_csr[i + 2]);
        int2 e3 = __ldg(&g_csr[i + 3]);
        uint4 r0 = *(const uint4*)(cur + (size_t)e0.x * NC + sub * 8);
        uint4 r1 = *(const uint4*)(cur + (size_t)e1.x * NC + sub * 8);
        uint4 r2 = *(const uint4*)(cur + (size_t)e2.x * NC + sub * 8);
        uint4 r3 = *(const uint4*)(cur + (size_t)e3.x * NC + sub * 8);
        mac8(acc, r0, __int_as_float(e0.y));
        mac8(acc, r1, __int_as_float(e1.y));
        mac8(acc, r2, __int_as_float(e2.y));
        mac8(acc, r3, __int_as_float(e3.y));
    }
    for (; i < e; i++) {
        int2 e0 = __ldg(&g_csr[i]);
        uint4 r0 = *(const uint4*)(cur + (size_t)e0.x * NC + sub * 8);
        mac8(acc, r0, __int_as_float(e0.y));
    }

    size_t off = (size_t)row * NC + sub * 8;

    // store next hop features as fp16
    uint4 packed;
    __half2* ph = (__half2*)&packed;
    ph[0] = __floats2half2_rn(acc[0], acc[1]);
    ph[1] = __floats2half2_rn(acc[2], acc[3]);
    ph[2] = __floats2half2_rn(acc[4], acc[5]);
    ph[3] = __floats2half2_rn(acc[6], acc[7]);
    *(uint4*)(next + off) = packed;

    // fused: out += w_hop * acc   (fp32)
    float w = g_weight[row * DEG + hop];
    float4 o0 = *(const float4*)(g_out + off);
    float4 o1 = *(const float4*)(g_out + off + 4);
    o0.x += w * acc[0]; o0.y += w * acc[1]; o0.z += w * acc[2]; o0.w += w * acc[3];
    o1.x += w * acc[4]; o1.y += w * acc[5]; o1.z += w * acc[6]; o1.w += w * acc[7];
    *(float4*)(g_out + off)     = o0;
    *(float4*)(g_out + off + 4) = o1;
}

// ---------------- final log_softmax ----------------
__global__ void k_final(float* __restrict__ dout) {
    int warp = (blockIdx.x * blockDim.x + threadIdx.x) >> 5;
    if (warp >= NN) return;
    int lane = threadIdx.x & 31;
    float2 t = *(const float2*)(g_out + (size_t)warp * NC + 2 * lane);
    float m = fmaxf(t.x, t.y);
    #pragma unroll
    for (int o = 16; o; o >>= 1) m = fmaxf(m, __shfl_xor_sync(~0u, m, o));
    float s = __expf(t.x - m) + __expf(t.y - m);
    #pragma unroll
    for (int o = 16; o; o >>= 1) s += __shfl_xor_sync(~0u, s, o);
    float l = m + __logf(s);
    *(float2*)(dout + (size_t)warp * NC + 2 * lane) = make_float2(t.x - l, t.y - l);
}

// ---------------- launch ----------------
extern "C" void kernel_launch(void* const* d_in, const int* in_sizes, int n_in,
                              void* d_out, int out_size) {
    const float* x  = (const float*)d_in[0];
    const int*   er = (const int*)d_in[1];
    const int*   ec = (const int*)d_in[2];
    const float* ev = (const float*)d_in[3];
    const float* W1 = (const float*)d_in[4];
    const float* b1 = (const float*)d_in[5];
    const float* W2 = (const float*)d_in[6];
    const float* b2 = (const float*)d_in[7];
    float* out = (float*)d_out;

    k_hist<<<(EE + 255) / 256, 256>>>(er);
    k_scan1<<<SCAN_NB, SCAN_BS>>>();
    k_scan2<<<1, 128>>>(SCAN_NB);
    k_scan3<<<SCAN_NB, SCAN_BS>>>();
    k_scatter<<<(EE + 255) / 256, 256>>>(er, ec, ev);

    k_gating<<<(NN * 32 + 255) / 256, 256>>>(x, W1, b1, W2, b2);

    k_spmm<<<(NN * 8 + 255) / 256, 256>>>(-1, 0, 1);
    k_spmm<<<(NN * 8 + 255) / 256, 256>>>(0, 1, 2);
    k_spmm<<<(NN * 8 + 255) / 256, 256>>>(1, 0, 3);
    k_spmm<<<(NN * 8 + 255) / 256, 256>>>(0, 1, 4);
    k_spmm<<<(NN * 8 + 255) / 256, 256>>>(1, 0, 5);

    k_final<<<(NN * 32 + 255) / 256, 256>>>(out);
}